// round 14
// baseline (speedup 1.0000x reference)
#include <cuda_runtime.h>
#include <math.h>
#include <stdint.h>

#define B   32
#define T0  16384
#define T1  8192
#define T2  4096
#define H   32
#define H2  64
#define ZD  64
#define KCB 1024

// ---------------- scratch (device globals; no runtime alloc) ----------------
__device__ float g_h1[B*H*T1];        // after conv1+lrelu   [b][32][8192]
__device__ float g_h2[B*H2*T2];       // after conv2+lrelu   [b][64][4096]
__device__ float g_z [B*ZD*T2];       // after conv3         [b][64][4096]
__device__ float g_quant[B*ZD*T2];    // q_st for decoder    [b][64][4096]
__device__ int   g_idx[B*T2];         // argmin indices
__device__ float g_d1[B*H2*T1];       // after deconv1+lrelu [b][64][8192]
__device__ float g_d2[B*H*T0];        // after deconv2+lrelu [b][32][16384]
__device__ float g_cn[KCB];           // codebook squared norms
__device__ float g_part[32768];       // loss partial sums (1024 used)

__device__ __forceinline__ float lrelu(float v){ return v > 0.f ? v : 0.2f*v; }

// ---- packed fp32x2 helpers (bit-exact: each half is IEEE fp32 rn) ----
__device__ __forceinline__ void ffma2(uint64_t &d, uint64_t a, uint64_t b){
    asm("fma.rn.f32x2 %0, %1, %2, %0;" : "+l"(d) : "l"(a), "l"(b));
}
__device__ __forceinline__ uint64_t dup2(float x){
    uint64_t r; asm("mov.b64 %0, {%1, %1};" : "=l"(r) : "f"(x)); return r;
}
__device__ __forceinline__ uint64_t pack2(float lo, float hi){
    uint64_t r; asm("mov.b64 %0, {%1, %2};" : "=l"(r) : "f"(lo), "f"(hi)); return r;
}
__device__ __forceinline__ void unpk(float &lo, float &hi, uint64_t v){
    asm("mov.b64 {%0, %1}, %2;" : "=f"(lo), "=f"(hi) : "l"(v));
}

// XLA row-reduce warp tree: partial -> shfl_down 16/8/4/2/1, result in lane 0.
__device__ __forceinline__ float warp_tree_sum(float p){
    #pragma unroll
    for (int off = 16; off > 0; off >>= 1)
        p = __fadd_rn(p, __shfl_down_sync(0xFFFFFFFFu, p, off));
    return p;
}

// ---------------- conv1 (+ fused codebook norms in extra blocks) ----------------
__global__ void k_conv1(const float* __restrict__ x, const float* __restrict__ w,
                        const float* __restrict__ bias, const float* __restrict__ cb){
    int tid = threadIdx.x;
    if (blockIdx.x >= 1024){
        int wid = ((blockIdx.x - 1024)*256 + tid) >> 5;   // code row, 1024 total
        int lid = tid & 31;
        float2 v = *(const float2*)&cb[wid*64 + 2*lid];
        float p = __fmul_rn(v.x, v.x);
        p = __fadd_rn(p, __fmul_rn(v.y, v.y));
        p = warp_tree_sum(p);
        if (lid == 0) g_cn[wid] = p;
        return;
    }
    __shared__ float sw[H*15];
    __shared__ float sb[H];
    for (int i = tid; i < H*15; i += blockDim.x) sw[i] = w[i];
    if (tid < H) sb[tid] = bias[tid];
    __syncthreads();
    int g = blockIdx.x*blockDim.x + tid;      // over B*T1
    int b = g >> 13, t = g & (T1-1);
    const float* xp = x + b*T0;
    float xv[15];
    int base = 2*t - 7;
    #pragma unroll
    for (int k = 0; k < 15; k++){ int p = base + k; xv[k] = (p >= 0 && p < T0) ? xp[p] : 0.f; }
    float* op = g_h1 + b*H*T1 + t;
    #pragma unroll
    for (int c = 0; c < H; c++){
        float a = 0.f;
        #pragma unroll
        for (int k = 0; k < 15; k++) a = fmaf(sw[c*15+k], xv[k], a);
        op[c*T1] = lrelu(a + sb[c]);
    }
}

// ---------------- conv2: 32->64, K=15, stride 2, pad 7 (f32x2, 512 thr) ----------------
#define CONV2_SM ((2*32*264 + 30720 + 64)*4)
__global__ void k_conv2(const float* __restrict__ w, const float* __restrict__ bias){
    extern __shared__ float sm[];
    float* sInE = sm;               // [32][264]  even positions
    float* sInO = sm + 32*264;      // [32][264]  odd positions
    float* sW2  = sm + 2*32*264;    // [k][ci][co] 15*32*64
    float* sb   = sW2 + 30720;      // 64
    int tid = threadIdx.x;
    int b  = blockIdx.y;
    int t0 = blockIdx.x*256;
    for (int i = tid; i < 30720; i += 512){
        int co = i/480, rem = i - co*480;
        int ci = rem/15, k = rem - ci*15;
        sW2[(k*32+ci)*64 + co] = w[i];
    }
    if (tid < 64) sb[tid] = bias[tid];
    int pbase = 2*t0 - 7;
    for (int i = tid; i < 32*525; i += 512){
        int ci = i/525, s = i - ci*525;
        int p  = pbase + s;
        float v = (p >= 0 && p < T1) ? g_h1[(b*32+ci)*T1 + p] : 0.f;
        if (s & 1) sInO[ci*264 + (s>>1)] = v;
        else       sInE[ci*264 + (s>>1)] = v;
    }
    __syncthreads();
    int tx = tid & 31, wrp = tid >> 5;
    int co0 = (wrp >> 1)*8;
    int tt0 = (wrp & 1)*128 + tx;
    uint64_t ap[4][4];
    #pragma unroll
    for (int pu = 0; pu < 4; pu++)
        #pragma unroll
        for (int j = 0; j < 4; j++) ap[pu][j] = 0ull;
    for (int k = 0; k < 15; k++){
        const float* xa = (k & 1) ? sInO : sInE;
        int kb = k >> 1;
        #pragma unroll 4
        for (int ci = 0; ci < 32; ci++){
            const ulonglong2* wp = (const ulonglong2*)&sW2[(k*32+ci)*64 + co0];
            ulonglong2 wA = wp[0];
            ulonglong2 wB = wp[1];
            float x0 = xa[ci*264 + tt0      + kb];
            float x1 = xa[ci*264 + tt0 + 32 + kb];
            float x2 = xa[ci*264 + tt0 + 64 + kb];
            float x3 = xa[ci*264 + tt0 + 96 + kb];
            uint64_t xd0 = dup2(x0), xd1 = dup2(x1), xd2 = dup2(x2), xd3 = dup2(x3);
            ffma2(ap[0][0], wA.x, xd0); ffma2(ap[0][1], wA.x, xd1); ffma2(ap[0][2], wA.x, xd2); ffma2(ap[0][3], wA.x, xd3);
            ffma2(ap[1][0], wA.y, xd0); ffma2(ap[1][1], wA.y, xd1); ffma2(ap[1][2], wA.y, xd2); ffma2(ap[1][3], wA.y, xd3);
            ffma2(ap[2][0], wB.x, xd0); ffma2(ap[2][1], wB.x, xd1); ffma2(ap[2][2], wB.x, xd2); ffma2(ap[2][3], wB.x, xd3);
            ffma2(ap[3][0], wB.y, xd0); ffma2(ap[3][1], wB.y, xd1); ffma2(ap[3][2], wB.y, xd2); ffma2(ap[3][3], wB.y, xd3);
        }
    }
    #pragma unroll
    for (int pu = 0; pu < 4; pu++){
        int coA = co0 + 2*pu, coB = coA + 1;
        float bA = sb[coA], bB = sb[coB];
        #pragma unroll
        for (int j = 0; j < 4; j++){
            float aA, aB;
            unpk(aA, aB, ap[pu][j]);
            int t = t0 + tt0 + 32*j;
            g_h2[(b*64+coA)*T2 + t] = lrelu(aA + bA);
            g_h2[(b*64+coB)*T2 + t] = lrelu(aB + bB);
        }
    }
}

// ---------------- conv3: 64->64, K=3, stride 1, pad 1 (f32x2, co-packed) ----------------
#define CONV3_SM ((64*132 + 12288 + 64)*4)
__global__ void k_conv3(const float* __restrict__ w, const float* __restrict__ bias){
    extern __shared__ float sm[];
    float* sIn = sm;               // 64 x 132 (span 130)
    float* sW3 = sm + 64*132;      // [k][ci][co] 3*64*64
    float* sb  = sW3 + 12288;
    int tid = threadIdx.x;
    int b  = blockIdx.y;
    int t0 = blockIdx.x*128;
    for (int i = tid; i < 12288; i += 256){
        int co = i/192, rem = i - co*192;
        int ci = rem/3, k = rem - ci*3;
        sW3[(k*64+ci)*64 + co] = w[i];
    }
    if (tid < 64) sb[tid] = bias[tid];
    int pbase = t0 - 1;
    for (int i = tid; i < 64*130; i += 256){
        int ci = i/130, s = i - ci*130;
        int p  = pbase + s;
        sIn[ci*132+s] = (p >= 0 && p < T2) ? g_h2[(b*64+ci)*T2 + p] : 0.f;
    }
    __syncthreads();
    int tx = tid & 31, ty = tid >> 5;
    int co0 = ty*8;
    uint64_t ap[4][4];
    #pragma unroll
    for (int pu = 0; pu < 4; pu++)
        #pragma unroll
        for (int j = 0; j < 4; j++) ap[pu][j] = 0ull;
    #pragma unroll
    for (int k = 0; k < 3; k++){
        #pragma unroll 4
        for (int ci = 0; ci < 64; ci++){
            const ulonglong2* wp = (const ulonglong2*)&sW3[(k*64+ci)*64 + co0];
            ulonglong2 wA = wp[0];
            ulonglong2 wB = wp[1];
            float x0 = sIn[ci*132 + tx      + k];
            float x1 = sIn[ci*132 + tx + 32 + k];
            float x2 = sIn[ci*132 + tx + 64 + k];
            float x3 = sIn[ci*132 + tx + 96 + k];
            uint64_t xd0 = dup2(x0), xd1 = dup2(x1), xd2 = dup2(x2), xd3 = dup2(x3);
            ffma2(ap[0][0], wA.x, xd0); ffma2(ap[0][1], wA.x, xd1); ffma2(ap[0][2], wA.x, xd2); ffma2(ap[0][3], wA.x, xd3);
            ffma2(ap[1][0], wA.y, xd0); ffma2(ap[1][1], wA.y, xd1); ffma2(ap[1][2], wA.y, xd2); ffma2(ap[1][3], wA.y, xd3);
            ffma2(ap[2][0], wB.x, xd0); ffma2(ap[2][1], wB.x, xd1); ffma2(ap[2][2], wB.x, xd2); ffma2(ap[2][3], wB.x, xd3);
            ffma2(ap[3][0], wB.y, xd0); ffma2(ap[3][1], wB.y, xd1); ffma2(ap[3][2], wB.y, xd2); ffma2(ap[3][3], wB.y, xd3);
        }
    }
    #pragma unroll
    for (int pu = 0; pu < 4; pu++){
        int coA = co0 + 2*pu, coB = coA + 1;
        float bA = sb[coA], bB = sb[coB];
        #pragma unroll
        for (int j = 0; j < 4; j++){
            float aA, aB;
            unpk(aA, aB, ap[pu][j]);
            int t = t0 + tx + 32*j;
            g_z[(b*64+coA)*T2 + t] = aA + bA;
            g_z[(b*64+coB)*T2 + t] = aB + bB;
        }
    }
}

// ---------------- VQ: 128 rows; 4 rows x 16 codes per warp per chunk ----------
// Code-pairs packed in b64; vectorized LDG.128 chunk staging.
// dist = fl(fl(zn+cn) - 2*dot), pure fp32; ties -> lowest index (ascending visit).
#define SZS 132
#define CT_S 132
#define VQ_SM ((64*SZS + 128 + 64*CT_S + 256)*4)
__global__ void k_vq(const float* __restrict__ cb, float* __restrict__ out_idxf){
    extern __shared__ float sm[];
    float* sZ  = sm;                  // [d][row] 64 x SZS (128 rows used)
    float* szn = sm + 64*SZS;         // 128 row norms
    float* sCbT= szn + 128;           // transposed chunk [64][CT_S] (128 codes)
    float* scn = sCbT + 64*CT_S;      // 128 code norms (+ loss partial area)
    float* redD = sCbT;               // reuse after chunks
    int*   redI = (int*)(sCbT + 1024);
    int*   sIdx = (int*)(sCbT + 2048);
    int tid = threadIdx.x;
    int row0 = blockIdx.x*128;
    int b  = row0 >> 12;
    int t0 = row0 & 4095;
    for (int i = tid; i < 8192; i += 256){
        int d = i >> 7, rr = i & 127;
        sZ[d*SZS + rr] = g_z[(b*64+d)*T2 + t0 + rr];
    }
    __syncthreads();
    int lane = tid & 31, w = tid >> 5;
    // zn: XLA row-reduce (lane l: fl(z[2l]^2 + z[2l+1]^2), then shfl tree)
    #pragma unroll
    for (int q = 0; q < 16; q++){
        int rr = w*16 + q;
        float v0 = sZ[(2*lane  )*SZS + rr];
        float v1 = sZ[(2*lane+1)*SZS + rr];
        float p = __fmul_rn(v0, v0);
        p = __fadd_rn(p, __fmul_rn(v1, v1));
        p = warp_tree_sum(p);
        if (lane == 0) szn[rr] = p;
    }
    __syncthreads();
    int rb = lane*4;
    float zn[4];
    #pragma unroll
    for (int i = 0; i < 4; i++) zn[i] = szn[rb+i];
    float bd[4] = {3.4e38f, 3.4e38f, 3.4e38f, 3.4e38f};
    int   bi[4] = {0,0,0,0};
    int c0 = w*16;                    // this warp's 16 codes within each chunk
    for (int ch = 0; ch < 8; ch++){
        // vectorized transpose staging: LDG.128 on cb rows, 4 scalar STS
        for (int i = tid; i < 2048; i += 256){
            int c = i >> 4, d0 = (i & 15)*4;
            float4 v = *(const float4*)&cb[(ch*128+c)*64 + d0];
            sCbT[(d0+0)*CT_S + c] = v.x;
            sCbT[(d0+1)*CT_S + c] = v.y;
            sCbT[(d0+2)*CT_S + c] = v.z;
            sCbT[(d0+3)*CT_S + c] = v.w;
        }
        if (tid < 128) scn[tid] = g_cn[ch*128 + tid];
        __syncthreads();
        uint64_t pr[4][8];
        #pragma unroll
        for (int i = 0; i < 4; i++)
            #pragma unroll
            for (int jp = 0; jp < 8; jp++) pr[i][jp] = 0ull;
        #pragma unroll 2
        for (int d = 0; d < 64; d++){
            float4 zv = *(const float4*)&sZ[d*SZS + rb];
            uint64_t zd0 = dup2(zv.x), zd1 = dup2(zv.y), zd2 = dup2(zv.z), zd3 = dup2(zv.w);
            ulonglong2 cpA = *(const ulonglong2*)&sCbT[d*CT_S + c0];
            ulonglong2 cpB = *(const ulonglong2*)&sCbT[d*CT_S + c0 + 4];
            ffma2(pr[0][0], zd0, cpA.x); ffma2(pr[1][0], zd1, cpA.x); ffma2(pr[2][0], zd2, cpA.x); ffma2(pr[3][0], zd3, cpA.x);
            ffma2(pr[0][1], zd0, cpA.y); ffma2(pr[1][1], zd1, cpA.y); ffma2(pr[2][1], zd2, cpA.y); ffma2(pr[3][1], zd3, cpA.y);
            ffma2(pr[0][2], zd0, cpB.x); ffma2(pr[1][2], zd1, cpB.x); ffma2(pr[2][2], zd2, cpB.x); ffma2(pr[3][2], zd3, cpB.x);
            ffma2(pr[0][3], zd0, cpB.y); ffma2(pr[1][3], zd1, cpB.y); ffma2(pr[2][3], zd2, cpB.y); ffma2(pr[3][3], zd3, cpB.y);
            ulonglong2 cpC = *(const ulonglong2*)&sCbT[d*CT_S + c0 + 8];
            ulonglong2 cpD = *(const ulonglong2*)&sCbT[d*CT_S + c0 + 12];
            ffma2(pr[0][4], zd0, cpC.x); ffma2(pr[1][4], zd1, cpC.x); ffma2(pr[2][4], zd2, cpC.x); ffma2(pr[3][4], zd3, cpC.x);
            ffma2(pr[0][5], zd0, cpC.y); ffma2(pr[1][5], zd1, cpC.y); ffma2(pr[2][5], zd2, cpC.y); ffma2(pr[3][5], zd3, cpC.y);
            ffma2(pr[0][6], zd0, cpD.x); ffma2(pr[1][6], zd1, cpD.x); ffma2(pr[2][6], zd2, cpD.x); ffma2(pr[3][6], zd3, cpD.x);
            ffma2(pr[0][7], zd0, cpD.y); ffma2(pr[1][7], zd1, cpD.y); ffma2(pr[2][7], zd2, cpD.y); ffma2(pr[3][7], zd3, cpD.y);
        }
        #pragma unroll
        for (int jp = 0; jp < 8; jp++){
            int gc0 = ch*128 + c0 + 2*jp;
            float cnL = scn[c0 + 2*jp];
            float cnH = scn[c0 + 2*jp + 1];
            #pragma unroll
            for (int i = 0; i < 4; i++){
                float aL, aH;
                unpk(aL, aH, pr[i][jp]);
                float sL = __fadd_rn(zn[i], cnL);
                float dL = __fsub_rn(sL, __fmul_rn(2.0f, aL));
                if (dL < bd[i]){ bd[i] = dL; bi[i] = gc0; }
                float sH = __fadd_rn(zn[i], cnH);
                float dH = __fsub_rn(sH, __fmul_rn(2.0f, aH));
                if (dH < bd[i]){ bd[i] = dH; bi[i] = gc0 + 1; }
            }
        }
        __syncthreads();
    }
    #pragma unroll
    for (int i = 0; i < 4; i++){ redD[w*128 + rb + i] = bd[i]; redI[w*128 + rb + i] = bi[i]; }
    __syncthreads();
    if (tid < 128){
        float d0 = redD[tid]; int i0 = redI[tid];
        #pragma unroll
        for (int g2 = 1; g2 < 8; g2++){
            float dg = redD[g2*128 + tid]; int ig = redI[g2*128 + tid];
            if (dg < d0 || (dg == d0 && ig < i0)){ d0 = dg; i0 = ig; }
        }
        g_idx[row0 + tid] = i0;
        out_idxf[row0 + tid] = (float)i0;
        sIdx[tid] = i0;
    }
    __syncthreads();
    // ---- fused gather + q_st + loss partial (z still in sZ) ----
    int row = tid & 127, dh = (tid >> 7)*32;
    int id = sIdx[row];
    const float* cq = cb + id*64 + dh;
    float lsum = 0.f;
    #pragma unroll 4
    for (int dq = 0; dq < 32; dq += 4){
        float4 q = *(const float4*)&cq[dq];
        float z0 = sZ[(dh+dq+0)*SZS + row];
        float z1 = sZ[(dh+dq+1)*SZS + row];
        float z2 = sZ[(dh+dq+2)*SZS + row];
        float z3 = sZ[(dh+dq+3)*SZS + row];
        float f0 = __fsub_rn(q.x, z0), f1 = __fsub_rn(q.y, z1);
        float f2 = __fsub_rn(q.z, z2), f3 = __fsub_rn(q.w, z3);
        g_quant[(b*64 + dh+dq+0)*T2 + t0 + row] = __fadd_rn(z0, f0);
        g_quant[(b*64 + dh+dq+1)*T2 + t0 + row] = __fadd_rn(z1, f1);
        g_quant[(b*64 + dh+dq+2)*T2 + t0 + row] = __fadd_rn(z2, f2);
        g_quant[(b*64 + dh+dq+3)*T2 + t0 + row] = __fadd_rn(z3, f3);
        lsum += f0*f0; lsum += f1*f1; lsum += f2*f2; lsum += f3*f3;
    }
    __syncthreads();
    scn[tid] = lsum;
    __syncthreads();
    for (int s = 128; s > 0; s >>= 1){
        if (tid < s) scn[tid] += scn[tid + s];
        __syncthreads();
    }
    if (tid == 0) g_part[blockIdx.x] = scn[0];
}

__global__ void k_loss(float* __restrict__ out){
    __shared__ float red[256];
    int tid = threadIdx.x;
    float a = 0.f;
    for (int i = tid; i < 1024; i += 256) a += g_part[i];
    red[tid] = a; __syncthreads();
    for (int s = 128; s > 0; s >>= 1){
        if (tid < s) red[tid] += red[tid + s];
        __syncthreads();
    }
    if (tid == 0) out[B*T0] = 1.25f * red[0] / 8388608.0f;
}

// ---------------- deconv1: ConvT 64->64, K=4, stride 2, pad 1 (f32x2, 512 thr) ----------------
#define DC1_SM ((64*132 + 16384 + 64)*4)
__global__ void k_deconv1(const float* __restrict__ w, const float* __restrict__ bias){
    extern __shared__ float sm[];
    float* sIn = sm;               // 64 x 132 (span 130: m0-1..m0+128)
    float* sW  = sm + 64*132;      // 64*64*4, k-swizzled
    float* sb  = sW + 16384;
    int tid = threadIdx.x;
    int b  = blockIdx.y;
    int m0 = blockIdx.x*128;
    for (int i = tid; i < 16384; i += 512) sW[i^1] = w[i];   // swizzle k: 0<->1, 2<->3
    if (tid < 64) sb[tid] = bias[tid];
    for (int i = tid; i < 64*130; i += 512){
        int ci = i/130, s = i - ci*130;
        int t = m0 - 1 + s;
        sIn[ci*132+s] = (t >= 0 && t < T2) ? g_quant[(b*64+ci)*T2 + t] : 0.f;
    }
    __syncthreads();
    int tx = tid & 31, wrp = tid >> 5;
    int co0 = (wrp >> 1)*8;
    int mh  = (wrp & 1)*64;
    uint64_t py[8][2];   // [u][j], packed {ye,yo}
    #pragma unroll
    for (int u = 0; u < 8; u++){ py[u][0] = 0ull; py[u][1] = 0ull; }
    for (int i = 0; i < 64; i++){
        uint64_t pA[2], pB[2];
        #pragma unroll
        for (int j = 0; j < 2; j++){
            int s = mh + tx + 32*j;
            float xm1 = sIn[i*132 + s];
            float xm  = sIn[i*132 + s + 1];
            float xp1 = sIn[i*132 + s + 2];
            pA[j] = pack2(xm, xp1);
            pB[j] = pack2(xm1, xm);
        }
        #pragma unroll
        for (int u = 0; u < 8; u++){
            ulonglong2 wp = *(const ulonglong2*)&sW[(i*64 + co0 + u)*4]; // {w1,w0},{w3,w2}
            #pragma unroll
            for (int j = 0; j < 2; j++){
                ffma2(py[u][j], pA[j], wp.x);
                ffma2(py[u][j], pB[j], wp.y);
            }
        }
    }
    #pragma unroll
    for (int u = 0; u < 8; u++){
        float bb = sb[co0+u];
        #pragma unroll
        for (int j = 0; j < 2; j++){
            int m = m0 + mh + tx + 32*j;
            float ye, yo;
            unpk(ye, yo, py[u][j]);
            float2 o;
            o.x = lrelu(ye + bb);
            o.y = lrelu(yo + bb);
            *(float2*)&g_d1[(b*64 + co0 + u)*T1 + 2*m] = o;
        }
    }
}

// ---------------- deconv2: ConvT 64->32, K=4, stride 2, pad 1 (f32x2, 512 thr) ----------------
#define DC2_SM ((64*264 + 8192 + 32)*4)
__global__ void k_deconv2(const float* __restrict__ w, const float* __restrict__ bias){
    extern __shared__ float sm[];
    float* sIn = sm;               // 64 x 264 (span 258: m0-1..m0+256)
    float* sW  = sm + 64*264;      // 64*32*4, k-swizzled
    float* sb  = sW + 8192;
    int tid = threadIdx.x;
    int b  = blockIdx.y;
    int m0 = blockIdx.x*256;
    for (int i = tid; i < 8192; i += 512) sW[i^1] = w[i];
    if (tid < 32) sb[tid] = bias[tid];
    for (int i = tid; i < 64*258; i += 512){
        int ci = i/258, s = i - ci*258;
        int t = m0 - 1 + s;
        sIn[ci*264+s] = (t >= 0 && t < T1) ? g_d1[(b*64+ci)*T1 + t] : 0.f;
    }
    __syncthreads();
    int tx = tid & 31, wrp = tid >> 5;
    int co0 = (wrp >> 1)*4;
    int mh  = (wrp & 1)*128;
    uint64_t py[4][4];   // [u][j], packed {ye,yo}
    #pragma unroll
    for (int u = 0; u < 4; u++)
        #pragma unroll
        for (int j = 0; j < 4; j++) py[u][j] = 0ull;
    for (int i = 0; i < 64; i++){
        uint64_t pA[4], pB[4];
        #pragma unroll
        for (int j = 0; j < 4; j++){
            int s = mh + tx + 32*j;
            float xm1 = sIn[i*264 + s];
            float xm  = sIn[i*264 + s + 1];
            float xp1 = sIn[i*264 + s + 2];
            pA[j] = pack2(xm, xp1);
            pB[j] = pack2(xm1, xm);
        }
        #pragma unroll
        for (int u = 0; u < 4; u++){
            ulonglong2 wp = *(const ulonglong2*)&sW[(i*32 + co0 + u)*4]; // {w1,w0},{w3,w2}
            #pragma unroll
            for (int j = 0; j < 4; j++){
                ffma2(py[u][j], pA[j], wp.x);
                ffma2(py[u][j], pB[j], wp.y);
            }
        }
    }
    #pragma unroll
    for (int u = 0; u < 4; u++){
        float bb = sb[co0+u];
        #pragma unroll
        for (int j = 0; j < 4; j++){
            int m = m0 + mh + tx + 32*j;
            float ye, yo;
            unpk(ye, yo, py[u][j]);
            float2 o;
            o.x = lrelu(ye + bb);
            o.y = lrelu(yo + bb);
            *(float2*)&g_d2[(b*32 + co0 + u)*T0 + 2*m] = o;
        }
    }
}

// ---------------- out conv: 32->1, K=7, pad 3, tanh (fp32) ----------------
#define OUT_SM ((32*264 + 224)*4)
__global__ void k_out(const float* __restrict__ w, const float* __restrict__ bias,
                      float* __restrict__ out){
    extern __shared__ float sm[];
    float* sIn = sm;               // 32 x 264 (span 262)
    float* sw  = sm + 32*264;      // 224
    __shared__ float sb0;
    int tid = threadIdx.x;
    int b  = blockIdx.y;
    int t0 = blockIdx.x*256;
    for (int i = tid; i < 224; i += 256) sw[i] = w[i];
    if (tid == 0) sb0 = bias[0];
    for (int i = tid; i < 32*262; i += 256){
        int ci = i/262, s = i - ci*262;
        int p  = t0 - 3 + s;
        sIn[ci*264+s] = (p >= 0 && p < T0) ? g_d2[(b*32+ci)*T0 + p] : 0.f;
    }
    __syncthreads();
    float a = 0.f;
    for (int ci = 0; ci < 32; ci++){
        #pragma unroll
        for (int k = 0; k < 7; k++) a = fmaf(sw[ci*7+k], sIn[ci*264 + tid + k], a);
    }
    out[b*T0 + t0 + tid] = tanhf(a + sb0);
}

// ---------------- launch ----------------
extern "C" void kernel_launch(void* const* d_in, const int* in_sizes, int n_in,
                              void* d_out, int out_size){
    (void)in_sizes; (void)n_in; (void)out_size;
    const float* x   = (const float*)d_in[0];
    const float* c1w = (const float*)d_in[1];
    const float* c1b = (const float*)d_in[2];
    const float* c2w = (const float*)d_in[3];
    const float* c2b = (const float*)d_in[4];
    const float* c3w = (const float*)d_in[5];
    const float* c3b = (const float*)d_in[6];
    const float* cb  = (const float*)d_in[7];
    const float* d1w = (const float*)d_in[8];
    const float* d1b = (const float*)d_in[9];
    const float* d2w = (const float*)d_in[10];
    const float* d2b = (const float*)d_in[11];
    const float* ow  = (const float*)d_in[12];
    const float* ob  = (const float*)d_in[13];
    float* out = (float*)d_out;

    cudaFuncSetAttribute(k_conv2,   cudaFuncAttributeMaxDynamicSharedMemorySize, CONV2_SM);
    cudaFuncSetAttribute(k_conv3,   cudaFuncAttributeMaxDynamicSharedMemorySize, CONV3_SM);
    cudaFuncSetAttribute(k_vq,      cudaFuncAttributeMaxDynamicSharedMemorySize, VQ_SM);
    cudaFuncSetAttribute(k_deconv1, cudaFuncAttributeMaxDynamicSharedMemorySize, DC1_SM);
    cudaFuncSetAttribute(k_deconv2, cudaFuncAttributeMaxDynamicSharedMemorySize, DC2_SM);
    cudaFuncSetAttribute(k_out,     cudaFuncAttributeMaxDynamicSharedMemorySize, OUT_SM);

    // k_vq is launch #4 -> lands in the ncu-profiled slot.
    k_conv1  <<<1152, 256>>>(x, c1w, c1b, cb);       // +128 blocks do cnorm
    k_conv2  <<<dim3(16,32), 512, CONV2_SM>>>(c2w, c2b);
    k_conv3  <<<dim3(32,32), 256, CONV3_SM>>>(c3w, c3b);
    k_vq     <<<1024, 256, VQ_SM>>>(cb, out + B*T0 + 1);
    k_loss   <<<1, 256>>>(out);
    k_deconv1<<<dim3(32,32), 512, DC1_SM>>>(d1w, d1b);
    k_deconv2<<<dim3(32,32), 512, DC2_SM>>>(d2w, d2b);   // FIX: 32 x-blocks (T1/256), was 16
    k_out    <<<dim3(64,32), 256, OUT_SM>>>(ow, ob, out);
}

// round 15
// speedup vs baseline: 1.0123x; 1.0123x over previous
#include <cuda_runtime.h>
#include <math.h>
#include <stdint.h>

#define B   32
#define T0  16384
#define T1  8192
#define T2  4096
#define H   32
#define H2  64
#define ZD  64
#define KCB 1024

// ---------------- scratch (device globals; no runtime alloc) ----------------
__device__ float g_h1[B*H*T1];        // after conv1+lrelu   [b][32][8192]
__device__ float g_h2[B*H2*T2];       // after conv2+lrelu   [b][64][4096]
__device__ float g_z [B*ZD*T2];       // after conv3         [b][64][4096]
__device__ float g_quant[B*ZD*T2];    // q_st for decoder    [b][64][4096]
__device__ int   g_idx[B*T2];         // argmin indices
__device__ float g_d1[B*H2*T1];       // after deconv1+lrelu [b][64][8192]
__device__ float g_d2[B*H*T0];        // after deconv2+lrelu [b][32][16384]
__device__ float g_cn[KCB];           // codebook squared norms
__device__ float g_part[32768];       // loss partial sums (1024 used)

__device__ __forceinline__ float lrelu(float v){ return v > 0.f ? v : 0.2f*v; }

// ---- packed fp32x2 helpers (bit-exact: each half is IEEE fp32 rn) ----
__device__ __forceinline__ void ffma2(uint64_t &d, uint64_t a, uint64_t b){
    asm("fma.rn.f32x2 %0, %1, %2, %0;" : "+l"(d) : "l"(a), "l"(b));
}
__device__ __forceinline__ uint64_t dup2(float x){
    uint64_t r; asm("mov.b64 %0, {%1, %1};" : "=l"(r) : "f"(x)); return r;
}
__device__ __forceinline__ uint64_t pack2(float lo, float hi){
    uint64_t r; asm("mov.b64 %0, {%1, %2};" : "=l"(r) : "f"(lo), "f"(hi)); return r;
}
__device__ __forceinline__ void unpk(float &lo, float &hi, uint64_t v){
    asm("mov.b64 {%0, %1}, %2;" : "=f"(lo), "=f"(hi) : "l"(v));
}

// XLA row-reduce warp tree: partial -> shfl_down 16/8/4/2/1, result in lane 0.
__device__ __forceinline__ float warp_tree_sum(float p){
    #pragma unroll
    for (int off = 16; off > 0; off >>= 1)
        p = __fadd_rn(p, __shfl_down_sync(0xFFFFFFFFu, p, off));
    return p;
}

// ---------------- conv1 (+ fused codebook norms in extra blocks) ----------------
__global__ void k_conv1(const float* __restrict__ x, const float* __restrict__ w,
                        const float* __restrict__ bias, const float* __restrict__ cb){
    int tid = threadIdx.x;
    if (blockIdx.x >= 1024){
        int wid = ((blockIdx.x - 1024)*256 + tid) >> 5;   // code row, 1024 total
        int lid = tid & 31;
        float2 v = *(const float2*)&cb[wid*64 + 2*lid];
        float p = __fmul_rn(v.x, v.x);
        p = __fadd_rn(p, __fmul_rn(v.y, v.y));
        p = warp_tree_sum(p);
        if (lid == 0) g_cn[wid] = p;
        return;
    }
    __shared__ float sw[H*15];
    __shared__ float sb[H];
    for (int i = tid; i < H*15; i += blockDim.x) sw[i] = w[i];
    if (tid < H) sb[tid] = bias[tid];
    __syncthreads();
    int g = blockIdx.x*blockDim.x + tid;      // over B*T1
    int b = g >> 13, t = g & (T1-1);
    const float* xp = x + b*T0;
    float xv[15];
    int base = 2*t - 7;
    #pragma unroll
    for (int k = 0; k < 15; k++){ int p = base + k; xv[k] = (p >= 0 && p < T0) ? xp[p] : 0.f; }
    float* op = g_h1 + b*H*T1 + t;
    #pragma unroll
    for (int c = 0; c < H; c++){
        float a = 0.f;
        #pragma unroll
        for (int k = 0; k < 15; k++) a = fmaf(sw[c*15+k], xv[k], a);
        op[c*T1] = lrelu(a + sb[c]);
    }
}

// ---------------- conv2: 32->64, K=15, stride 2, pad 7 (f32x2, 512 thr) ----------------
#define CONV2_SM ((2*32*264 + 30720 + 64)*4)
__global__ void k_conv2(const float* __restrict__ w, const float* __restrict__ bias){
    extern __shared__ float sm[];
    float* sInE = sm;               // [32][264]  even positions
    float* sInO = sm + 32*264;      // [32][264]  odd positions
    float* sW2  = sm + 2*32*264;    // [k][ci][co] 15*32*64
    float* sb   = sW2 + 30720;      // 64
    int tid = threadIdx.x;
    int b  = blockIdx.y;
    int t0 = blockIdx.x*256;
    for (int i = tid; i < 30720; i += 512){
        int co = i/480, rem = i - co*480;
        int ci = rem/15, k = rem - ci*15;
        sW2[(k*32+ci)*64 + co] = w[i];
    }
    if (tid < 64) sb[tid] = bias[tid];
    int pbase = 2*t0 - 7;
    for (int i = tid; i < 32*525; i += 512){
        int ci = i/525, s = i - ci*525;
        int p  = pbase + s;
        float v = (p >= 0 && p < T1) ? g_h1[(b*32+ci)*T1 + p] : 0.f;
        if (s & 1) sInO[ci*264 + (s>>1)] = v;
        else       sInE[ci*264 + (s>>1)] = v;
    }
    __syncthreads();
    int tx = tid & 31, wrp = tid >> 5;
    int co0 = (wrp >> 1)*8;
    int tt0 = (wrp & 1)*128 + tx;
    uint64_t ap[4][4];
    #pragma unroll
    for (int pu = 0; pu < 4; pu++)
        #pragma unroll
        for (int j = 0; j < 4; j++) ap[pu][j] = 0ull;
    for (int k = 0; k < 15; k++){
        const float* xa = (k & 1) ? sInO : sInE;
        int kb = k >> 1;
        #pragma unroll 4
        for (int ci = 0; ci < 32; ci++){
            const ulonglong2* wp = (const ulonglong2*)&sW2[(k*32+ci)*64 + co0];
            ulonglong2 wA = wp[0];
            ulonglong2 wB = wp[1];
            float x0 = xa[ci*264 + tt0      + kb];
            float x1 = xa[ci*264 + tt0 + 32 + kb];
            float x2 = xa[ci*264 + tt0 + 64 + kb];
            float x3 = xa[ci*264 + tt0 + 96 + kb];
            uint64_t xd0 = dup2(x0), xd1 = dup2(x1), xd2 = dup2(x2), xd3 = dup2(x3);
            ffma2(ap[0][0], wA.x, xd0); ffma2(ap[0][1], wA.x, xd1); ffma2(ap[0][2], wA.x, xd2); ffma2(ap[0][3], wA.x, xd3);
            ffma2(ap[1][0], wA.y, xd0); ffma2(ap[1][1], wA.y, xd1); ffma2(ap[1][2], wA.y, xd2); ffma2(ap[1][3], wA.y, xd3);
            ffma2(ap[2][0], wB.x, xd0); ffma2(ap[2][1], wB.x, xd1); ffma2(ap[2][2], wB.x, xd2); ffma2(ap[2][3], wB.x, xd3);
            ffma2(ap[3][0], wB.y, xd0); ffma2(ap[3][1], wB.y, xd1); ffma2(ap[3][2], wB.y, xd2); ffma2(ap[3][3], wB.y, xd3);
        }
    }
    #pragma unroll
    for (int pu = 0; pu < 4; pu++){
        int coA = co0 + 2*pu, coB = coA + 1;
        float bA = sb[coA], bB = sb[coB];
        #pragma unroll
        for (int j = 0; j < 4; j++){
            float aA, aB;
            unpk(aA, aB, ap[pu][j]);
            int t = t0 + tt0 + 32*j;
            g_h2[(b*64+coA)*T2 + t] = lrelu(aA + bA);
            g_h2[(b*64+coB)*T2 + t] = lrelu(aB + bB);
        }
    }
}

// ---------------- conv3: 64->64, K=3, stride 1, pad 1 (f32x2, co-packed) ----------------
#define CONV3_SM ((64*132 + 12288 + 64)*4)
__global__ void k_conv3(const float* __restrict__ w, const float* __restrict__ bias){
    extern __shared__ float sm[];
    float* sIn = sm;               // 64 x 132 (span 130)
    float* sW3 = sm + 64*132;      // [k][ci][co] 3*64*64
    float* sb  = sW3 + 12288;
    int tid = threadIdx.x;
    int b  = blockIdx.y;
    int t0 = blockIdx.x*128;
    for (int i = tid; i < 12288; i += 256){
        int co = i/192, rem = i - co*192;
        int ci = rem/3, k = rem - ci*3;
        sW3[(k*64+ci)*64 + co] = w[i];
    }
    if (tid < 64) sb[tid] = bias[tid];
    int pbase = t0 - 1;
    for (int i = tid; i < 64*130; i += 256){
        int ci = i/130, s = i - ci*130;
        int p  = pbase + s;
        sIn[ci*132+s] = (p >= 0 && p < T2) ? g_h2[(b*64+ci)*T2 + p] : 0.f;
    }
    __syncthreads();
    int tx = tid & 31, ty = tid >> 5;
    int co0 = ty*8;
    uint64_t ap[4][4];
    #pragma unroll
    for (int pu = 0; pu < 4; pu++)
        #pragma unroll
        for (int j = 0; j < 4; j++) ap[pu][j] = 0ull;
    #pragma unroll
    for (int k = 0; k < 3; k++){
        #pragma unroll 4
        for (int ci = 0; ci < 64; ci++){
            const ulonglong2* wp = (const ulonglong2*)&sW3[(k*64+ci)*64 + co0];
            ulonglong2 wA = wp[0];
            ulonglong2 wB = wp[1];
            float x0 = sIn[ci*132 + tx      + k];
            float x1 = sIn[ci*132 + tx + 32 + k];
            float x2 = sIn[ci*132 + tx + 64 + k];
            float x3 = sIn[ci*132 + tx + 96 + k];
            uint64_t xd0 = dup2(x0), xd1 = dup2(x1), xd2 = dup2(x2), xd3 = dup2(x3);
            ffma2(ap[0][0], wA.x, xd0); ffma2(ap[0][1], wA.x, xd1); ffma2(ap[0][2], wA.x, xd2); ffma2(ap[0][3], wA.x, xd3);
            ffma2(ap[1][0], wA.y, xd0); ffma2(ap[1][1], wA.y, xd1); ffma2(ap[1][2], wA.y, xd2); ffma2(ap[1][3], wA.y, xd3);
            ffma2(ap[2][0], wB.x, xd0); ffma2(ap[2][1], wB.x, xd1); ffma2(ap[2][2], wB.x, xd2); ffma2(ap[2][3], wB.x, xd3);
            ffma2(ap[3][0], wB.y, xd0); ffma2(ap[3][1], wB.y, xd1); ffma2(ap[3][2], wB.y, xd2); ffma2(ap[3][3], wB.y, xd3);
        }
    }
    #pragma unroll
    for (int pu = 0; pu < 4; pu++){
        int coA = co0 + 2*pu, coB = coA + 1;
        float bA = sb[coA], bB = sb[coB];
        #pragma unroll
        for (int j = 0; j < 4; j++){
            float aA, aB;
            unpk(aA, aB, ap[pu][j]);
            int t = t0 + tx + 32*j;
            g_z[(b*64+coA)*T2 + t] = aA + bA;
            g_z[(b*64+coB)*T2 + t] = aB + bB;
        }
    }
}

// ---------------- VQ: 128 rows; 4 rows x 16 codes per warp per chunk ----------
// Code-pairs packed in b64; scalar chunk staging (R12-proven: coalesced LDG).
// dist = fl(fl(zn+cn) - 2*dot), pure fp32; ties -> lowest index (ascending visit).
#define SZS 132
#define CT_S 132
#define VQ_SM ((64*SZS + 128 + 64*CT_S + 256)*4)
__global__ void k_vq(const float* __restrict__ cb, float* __restrict__ out_idxf){
    extern __shared__ float sm[];
    float* sZ  = sm;                  // [d][row] 64 x SZS (128 rows used)
    float* szn = sm + 64*SZS;         // 128 row norms
    float* sCbT= szn + 128;           // transposed chunk [64][CT_S] (128 codes)
    float* scn = sCbT + 64*CT_S;      // 128 code norms (+ loss partial area)
    float* redD = sCbT;               // reuse after chunks
    int*   redI = (int*)(sCbT + 1024);
    int*   sIdx = (int*)(sCbT + 2048);
    int tid = threadIdx.x;
    int row0 = blockIdx.x*128;
    int b  = row0 >> 12;
    int t0 = row0 & 4095;
    for (int i = tid; i < 8192; i += 256){
        int d = i >> 7, rr = i & 127;
        sZ[d*SZS + rr] = g_z[(b*64+d)*T2 + t0 + rr];
    }
    __syncthreads();
    int lane = tid & 31, w = tid >> 5;
    // zn: XLA row-reduce (lane l: fl(z[2l]^2 + z[2l+1]^2), then shfl tree)
    #pragma unroll
    for (int q = 0; q < 16; q++){
        int rr = w*16 + q;
        float v0 = sZ[(2*lane  )*SZS + rr];
        float v1 = sZ[(2*lane+1)*SZS + rr];
        float p = __fmul_rn(v0, v0);
        p = __fadd_rn(p, __fmul_rn(v1, v1));
        p = warp_tree_sum(p);
        if (lane == 0) szn[rr] = p;
    }
    __syncthreads();
    int rb = lane*4;
    float zn[4];
    #pragma unroll
    for (int i = 0; i < 4; i++) zn[i] = szn[rb+i];
    float bd[4] = {3.4e38f, 3.4e38f, 3.4e38f, 3.4e38f};
    int   bi[4] = {0,0,0,0};
    int c0 = w*16;                    // this warp's 16 codes within each chunk
    for (int ch = 0; ch < 8; ch++){
        // scalar transpose staging (R12): coalesced LDG, 4-way STS
        for (int i = tid; i < 8192; i += 256){
            int d = i & 63, c = i >> 6;
            sCbT[d*CT_S + c] = cb[(ch*128+c)*64 + d];
        }
        if (tid < 128) scn[tid] = g_cn[ch*128 + tid];
        __syncthreads();
        uint64_t pr[4][8];
        #pragma unroll
        for (int i = 0; i < 4; i++)
            #pragma unroll
            for (int jp = 0; jp < 8; jp++) pr[i][jp] = 0ull;
        #pragma unroll 2
        for (int d = 0; d < 64; d++){
            float4 zv = *(const float4*)&sZ[d*SZS + rb];
            uint64_t zd0 = dup2(zv.x), zd1 = dup2(zv.y), zd2 = dup2(zv.z), zd3 = dup2(zv.w);
            ulonglong2 cpA = *(const ulonglong2*)&sCbT[d*CT_S + c0];
            ulonglong2 cpB = *(const ulonglong2*)&sCbT[d*CT_S + c0 + 4];
            ffma2(pr[0][0], zd0, cpA.x); ffma2(pr[1][0], zd1, cpA.x); ffma2(pr[2][0], zd2, cpA.x); ffma2(pr[3][0], zd3, cpA.x);
            ffma2(pr[0][1], zd0, cpA.y); ffma2(pr[1][1], zd1, cpA.y); ffma2(pr[2][1], zd2, cpA.y); ffma2(pr[3][1], zd3, cpA.y);
            ffma2(pr[0][2], zd0, cpB.x); ffma2(pr[1][2], zd1, cpB.x); ffma2(pr[2][2], zd2, cpB.x); ffma2(pr[3][2], zd3, cpB.x);
            ffma2(pr[0][3], zd0, cpB.y); ffma2(pr[1][3], zd1, cpB.y); ffma2(pr[2][3], zd2, cpB.y); ffma2(pr[3][3], zd3, cpB.y);
            ulonglong2 cpC = *(const ulonglong2*)&sCbT[d*CT_S + c0 + 8];
            ulonglong2 cpD = *(const ulonglong2*)&sCbT[d*CT_S + c0 + 12];
            ffma2(pr[0][4], zd0, cpC.x); ffma2(pr[1][4], zd1, cpC.x); ffma2(pr[2][4], zd2, cpC.x); ffma2(pr[3][4], zd3, cpC.x);
            ffma2(pr[0][5], zd0, cpC.y); ffma2(pr[1][5], zd1, cpC.y); ffma2(pr[2][5], zd2, cpC.y); ffma2(pr[3][5], zd3, cpC.y);
            ffma2(pr[0][6], zd0, cpD.x); ffma2(pr[1][6], zd1, cpD.x); ffma2(pr[2][6], zd2, cpD.x); ffma2(pr[3][6], zd3, cpD.x);
            ffma2(pr[0][7], zd0, cpD.y); ffma2(pr[1][7], zd1, cpD.y); ffma2(pr[2][7], zd2, cpD.y); ffma2(pr[3][7], zd3, cpD.y);
        }
        #pragma unroll
        for (int jp = 0; jp < 8; jp++){
            int gc0 = ch*128 + c0 + 2*jp;
            float cnL = scn[c0 + 2*jp];
            float cnH = scn[c0 + 2*jp + 1];
            #pragma unroll
            for (int i = 0; i < 4; i++){
                float aL, aH;
                unpk(aL, aH, pr[i][jp]);
                float sL = __fadd_rn(zn[i], cnL);
                float dL = __fsub_rn(sL, __fmul_rn(2.0f, aL));
                if (dL < bd[i]){ bd[i] = dL; bi[i] = gc0; }
                float sH = __fadd_rn(zn[i], cnH);
                float dH = __fsub_rn(sH, __fmul_rn(2.0f, aH));
                if (dH < bd[i]){ bd[i] = dH; bi[i] = gc0 + 1; }
            }
        }
        __syncthreads();
    }
    #pragma unroll
    for (int i = 0; i < 4; i++){ redD[w*128 + rb + i] = bd[i]; redI[w*128 + rb + i] = bi[i]; }
    __syncthreads();
    if (tid < 128){
        float d0 = redD[tid]; int i0 = redI[tid];
        #pragma unroll
        for (int g2 = 1; g2 < 8; g2++){
            float dg = redD[g2*128 + tid]; int ig = redI[g2*128 + tid];
            if (dg < d0 || (dg == d0 && ig < i0)){ d0 = dg; i0 = ig; }
        }
        g_idx[row0 + tid] = i0;
        out_idxf[row0 + tid] = (float)i0;
        sIdx[tid] = i0;
    }
    __syncthreads();
    // ---- fused gather + q_st + loss partial (z still in sZ) ----
    int row = tid & 127, dh = (tid >> 7)*32;
    int id = sIdx[row];
    const float* cq = cb + id*64 + dh;
    float lsum = 0.f;
    #pragma unroll 4
    for (int dq = 0; dq < 32; dq += 4){
        float4 q = *(const float4*)&cq[dq];
        float z0 = sZ[(dh+dq+0)*SZS + row];
        float z1 = sZ[(dh+dq+1)*SZS + row];
        float z2 = sZ[(dh+dq+2)*SZS + row];
        float z3 = sZ[(dh+dq+3)*SZS + row];
        float f0 = __fsub_rn(q.x, z0), f1 = __fsub_rn(q.y, z1);
        float f2 = __fsub_rn(q.z, z2), f3 = __fsub_rn(q.w, z3);
        g_quant[(b*64 + dh+dq+0)*T2 + t0 + row] = __fadd_rn(z0, f0);
        g_quant[(b*64 + dh+dq+1)*T2 + t0 + row] = __fadd_rn(z1, f1);
        g_quant[(b*64 + dh+dq+2)*T2 + t0 + row] = __fadd_rn(z2, f2);
        g_quant[(b*64 + dh+dq+3)*T2 + t0 + row] = __fadd_rn(z3, f3);
        lsum += f0*f0; lsum += f1*f1; lsum += f2*f2; lsum += f3*f3;
    }
    __syncthreads();
    scn[tid] = lsum;
    __syncthreads();
    for (int s = 128; s > 0; s >>= 1){
        if (tid < s) scn[tid] += scn[tid + s];
        __syncthreads();
    }
    if (tid == 0) g_part[blockIdx.x] = scn[0];
}

__global__ void k_loss(float* __restrict__ out){
    __shared__ float red[256];
    int tid = threadIdx.x;
    float a = 0.f;
    for (int i = tid; i < 1024; i += 256) a += g_part[i];
    red[tid] = a; __syncthreads();
    for (int s = 128; s > 0; s >>= 1){
        if (tid < s) red[tid] += red[tid + s];
        __syncthreads();
    }
    if (tid == 0) out[B*T0] = 1.25f * red[0] / 8388608.0f;
}

// ---------------- deconv1: ConvT 64->64, K=4, stride 2, pad 1 (f32x2, 512 thr) ----------------
#define DC1_SM ((64*132 + 16384 + 64)*4)
__global__ void k_deconv1(const float* __restrict__ w, const float* __restrict__ bias){
    extern __shared__ float sm[];
    float* sIn = sm;               // 64 x 132 (span 130: m0-1..m0+128)
    float* sW  = sm + 64*132;      // 64*64*4, k-swizzled
    float* sb  = sW + 16384;
    int tid = threadIdx.x;
    int b  = blockIdx.y;
    int m0 = blockIdx.x*128;
    for (int i = tid; i < 16384; i += 512) sW[i^1] = w[i];   // swizzle k: 0<->1, 2<->3
    if (tid < 64) sb[tid] = bias[tid];
    for (int i = tid; i < 64*130; i += 512){
        int ci = i/130, s = i - ci*130;
        int t = m0 - 1 + s;
        sIn[ci*132+s] = (t >= 0 && t < T2) ? g_quant[(b*64+ci)*T2 + t] : 0.f;
    }
    __syncthreads();
    int tx = tid & 31, wrp = tid >> 5;
    int co0 = (wrp >> 1)*8;
    int mh  = (wrp & 1)*64;
    uint64_t py[8][2];   // [u][j], packed {ye,yo}
    #pragma unroll
    for (int u = 0; u < 8; u++){ py[u][0] = 0ull; py[u][1] = 0ull; }
    for (int i = 0; i < 64; i++){
        uint64_t pA[2], pB[2];
        #pragma unroll
        for (int j = 0; j < 2; j++){
            int s = mh + tx + 32*j;
            float xm1 = sIn[i*132 + s];
            float xm  = sIn[i*132 + s + 1];
            float xp1 = sIn[i*132 + s + 2];
            pA[j] = pack2(xm, xp1);
            pB[j] = pack2(xm1, xm);
        }
        #pragma unroll
        for (int u = 0; u < 8; u++){
            ulonglong2 wp = *(const ulonglong2*)&sW[(i*64 + co0 + u)*4]; // {w1,w0},{w3,w2}
            #pragma unroll
            for (int j = 0; j < 2; j++){
                ffma2(py[u][j], pA[j], wp.x);
                ffma2(py[u][j], pB[j], wp.y);
            }
        }
    }
    #pragma unroll
    for (int u = 0; u < 8; u++){
        float bb = sb[co0+u];
        #pragma unroll
        for (int j = 0; j < 2; j++){
            int m = m0 + mh + tx + 32*j;
            float ye, yo;
            unpk(ye, yo, py[u][j]);
            float2 o;
            o.x = lrelu(ye + bb);
            o.y = lrelu(yo + bb);
            *(float2*)&g_d1[(b*64 + co0 + u)*T1 + 2*m] = o;
        }
    }
}

// ---------------- deconv2: ConvT 64->32, K=4, stride 2, pad 1 (f32x2, 512 thr) ----------------
#define DC2_SM ((64*264 + 8192 + 32)*4)
__global__ void k_deconv2(const float* __restrict__ w, const float* __restrict__ bias){
    extern __shared__ float sm[];
    float* sIn = sm;               // 64 x 264 (span 258: m0-1..m0+256)
    float* sW  = sm + 64*264;      // 64*32*4, k-swizzled
    float* sb  = sW + 8192;
    int tid = threadIdx.x;
    int b  = blockIdx.y;
    int m0 = blockIdx.x*256;
    for (int i = tid; i < 8192; i += 512) sW[i^1] = w[i];
    if (tid < 32) sb[tid] = bias[tid];
    for (int i = tid; i < 64*258; i += 512){
        int ci = i/258, s = i - ci*258;
        int t = m0 - 1 + s;
        sIn[ci*264+s] = (t >= 0 && t < T1) ? g_d1[(b*64+ci)*T1 + t] : 0.f;
    }
    __syncthreads();
    int tx = tid & 31, wrp = tid >> 5;
    int co0 = (wrp >> 1)*4;
    int mh  = (wrp & 1)*128;
    uint64_t py[4][4];   // [u][j], packed {ye,yo}
    #pragma unroll
    for (int u = 0; u < 4; u++)
        #pragma unroll
        for (int j = 0; j < 4; j++) py[u][j] = 0ull;
    for (int i = 0; i < 64; i++){
        uint64_t pA[4], pB[4];
        #pragma unroll
        for (int j = 0; j < 4; j++){
            int s = mh + tx + 32*j;
            float xm1 = sIn[i*264 + s];
            float xm  = sIn[i*264 + s + 1];
            float xp1 = sIn[i*264 + s + 2];
            pA[j] = pack2(xm, xp1);
            pB[j] = pack2(xm1, xm);
        }
        #pragma unroll
        for (int u = 0; u < 4; u++){
            ulonglong2 wp = *(const ulonglong2*)&sW[(i*32 + co0 + u)*4]; // {w1,w0},{w3,w2}
            #pragma unroll
            for (int j = 0; j < 4; j++){
                ffma2(py[u][j], pA[j], wp.x);
                ffma2(py[u][j], pB[j], wp.y);
            }
        }
    }
    #pragma unroll
    for (int u = 0; u < 4; u++){
        float bb = sb[co0+u];
        #pragma unroll
        for (int j = 0; j < 4; j++){
            int m = m0 + mh + tx + 32*j;
            float ye, yo;
            unpk(ye, yo, py[u][j]);
            float2 o;
            o.x = lrelu(ye + bb);
            o.y = lrelu(yo + bb);
            *(float2*)&g_d2[(b*32 + co0 + u)*T0 + 2*m] = o;
        }
    }
}

// ---------------- out conv: 32->1, K=7, pad 3, tanh (fp32) ----------------
#define OUT_SM ((32*264 + 224)*4)
__global__ void k_out(const float* __restrict__ w, const float* __restrict__ bias,
                      float* __restrict__ out){
    extern __shared__ float sm[];
    float* sIn = sm;               // 32 x 264 (span 262)
    float* sw  = sm + 32*264;      // 224
    __shared__ float sb0;
    int tid = threadIdx.x;
    int b  = blockIdx.y;
    int t0 = blockIdx.x*256;
    for (int i = tid; i < 224; i += 256) sw[i] = w[i];
    if (tid == 0) sb0 = bias[0];
    for (int i = tid; i < 32*262; i += 256){
        int ci = i/262, s = i - ci*262;
        int p  = t0 - 3 + s;
        sIn[ci*264+s] = (p >= 0 && p < T0) ? g_d2[(b*32+ci)*T0 + p] : 0.f;
    }
    __syncthreads();
    float a = 0.f;
    for (int ci = 0; ci < 32; ci++){
        #pragma unroll
        for (int k = 0; k < 7; k++) a = fmaf(sw[ci*7+k], sIn[ci*264 + tid + k], a);
    }
    out[b*T0 + t0 + tid] = tanhf(a + sb0);
}

// ---------------- launch ----------------
extern "C" void kernel_launch(void* const* d_in, const int* in_sizes, int n_in,
                              void* d_out, int out_size){
    (void)in_sizes; (void)n_in; (void)out_size;
    const float* x   = (const float*)d_in[0];
    const float* c1w = (const float*)d_in[1];
    const float* c1b = (const float*)d_in[2];
    const float* c2w = (const float*)d_in[3];
    const float* c2b = (const float*)d_in[4];
    const float* c3w = (const float*)d_in[5];
    const float* c3b = (const float*)d_in[6];
    const float* cb  = (const float*)d_in[7];
    const float* d1w = (const float*)d_in[8];
    const float* d1b = (const float*)d_in[9];
    const float* d2w = (const float*)d_in[10];
    const float* d2b = (const float*)d_in[11];
    const float* ow  = (const float*)d_in[12];
    const float* ob  = (const float*)d_in[13];
    float* out = (float*)d_out;

    cudaFuncSetAttribute(k_conv2,   cudaFuncAttributeMaxDynamicSharedMemorySize, CONV2_SM);
    cudaFuncSetAttribute(k_conv3,   cudaFuncAttributeMaxDynamicSharedMemorySize, CONV3_SM);
    cudaFuncSetAttribute(k_vq,      cudaFuncAttributeMaxDynamicSharedMemorySize, VQ_SM);
    cudaFuncSetAttribute(k_deconv1, cudaFuncAttributeMaxDynamicSharedMemorySize, DC1_SM);
    cudaFuncSetAttribute(k_deconv2, cudaFuncAttributeMaxDynamicSharedMemorySize, DC2_SM);
    cudaFuncSetAttribute(k_out,     cudaFuncAttributeMaxDynamicSharedMemorySize, OUT_SM);

    // k_vq is launch #4 -> lands in the ncu-profiled slot.
    k_conv1  <<<1152, 256>>>(x, c1w, c1b, cb);       // +128 blocks do cnorm
    k_conv2  <<<dim3(16,32), 512, CONV2_SM>>>(c2w, c2b);
    k_conv3  <<<dim3(32,32), 256, CONV3_SM>>>(c3w, c3b);
    k_vq     <<<1024, 256, VQ_SM>>>(cb, out + B*T0 + 1);
    k_loss   <<<1, 256>>>(out);
    k_deconv1<<<dim3(32,32), 512, DC1_SM>>>(d1w, d1b);
    k_deconv2<<<dim3(32,32), 512, DC2_SM>>>(d2w, d2b);
    k_out    <<<dim3(64,32), 256, OUT_SM>>>(ow, ob, out);
}

// round 16
// speedup vs baseline: 1.0277x; 1.0152x over previous
#include <cuda_runtime.h>
#include <math.h>
#include <stdint.h>

#define B   32
#define T0  16384
#define T1  8192
#define T2  4096
#define H   32
#define H2  64
#define ZD  64
#define KCB 1024

// ---------------- scratch (device globals; no runtime alloc) ----------------
__device__ float g_h1[B*H*T1];        // after conv1+lrelu   [b][32][8192]
__device__ float g_h2[B*H2*T2];       // after conv2+lrelu   [b][64][4096]
__device__ float g_z [B*ZD*T2];       // after conv3         [b][64][4096]
__device__ float g_quant[B*ZD*T2];    // q_st for decoder    [b][64][4096]
__device__ int   g_idx[B*T2];         // argmin indices
__device__ float g_d1[B*H2*T1];       // after deconv1+lrelu [b][64][8192]
__device__ float g_cn[KCB];           // codebook squared norms
__device__ float g_part[32768];       // loss partial sums (1024 used)

__device__ __forceinline__ float lrelu(float v){ return v > 0.f ? v : 0.2f*v; }

// ---- packed fp32x2 helpers (bit-exact: each half is IEEE fp32 rn) ----
__device__ __forceinline__ void ffma2(uint64_t &d, uint64_t a, uint64_t b){
    asm("fma.rn.f32x2 %0, %1, %2, %0;" : "+l"(d) : "l"(a), "l"(b));
}
__device__ __forceinline__ uint64_t dup2(float x){
    uint64_t r; asm("mov.b64 %0, {%1, %1};" : "=l"(r) : "f"(x)); return r;
}
__device__ __forceinline__ uint64_t pack2(float lo, float hi){
    uint64_t r; asm("mov.b64 %0, {%1, %2};" : "=l"(r) : "f"(lo), "f"(hi)); return r;
}
__device__ __forceinline__ void unpk(float &lo, float &hi, uint64_t v){
    asm("mov.b64 {%0, %1}, %2;" : "=f"(lo), "=f"(hi) : "l"(v));
}

// XLA row-reduce warp tree: partial -> shfl_down 16/8/4/2/1, result in lane 0.
__device__ __forceinline__ float warp_tree_sum(float p){
    #pragma unroll
    for (int off = 16; off > 0; off >>= 1)
        p = __fadd_rn(p, __shfl_down_sync(0xFFFFFFFFu, p, off));
    return p;
}

// ---------------- conv1 (+ fused codebook norms in extra blocks) ----------------
__global__ void k_conv1(const float* __restrict__ x, const float* __restrict__ w,
                        const float* __restrict__ bias, const float* __restrict__ cb){
    int tid = threadIdx.x;
    if (blockIdx.x >= 1024){
        int wid = ((blockIdx.x - 1024)*256 + tid) >> 5;   // code row, 1024 total
        int lid = tid & 31;
        float2 v = *(const float2*)&cb[wid*64 + 2*lid];
        float p = __fmul_rn(v.x, v.x);
        p = __fadd_rn(p, __fmul_rn(v.y, v.y));
        p = warp_tree_sum(p);
        if (lid == 0) g_cn[wid] = p;
        return;
    }
    __shared__ float sw[H*15];
    __shared__ float sb[H];
    for (int i = tid; i < H*15; i += blockDim.x) sw[i] = w[i];
    if (tid < H) sb[tid] = bias[tid];
    __syncthreads();
    int g = blockIdx.x*blockDim.x + tid;      // over B*T1
    int b = g >> 13, t = g & (T1-1);
    const float* xp = x + b*T0;
    float xv[15];
    int base = 2*t - 7;
    #pragma unroll
    for (int k = 0; k < 15; k++){ int p = base + k; xv[k] = (p >= 0 && p < T0) ? xp[p] : 0.f; }
    float* op = g_h1 + b*H*T1 + t;
    #pragma unroll
    for (int c = 0; c < H; c++){
        float a = 0.f;
        #pragma unroll
        for (int k = 0; k < 15; k++) a = fmaf(sw[c*15+k], xv[k], a);
        op[c*T1] = lrelu(a + sb[c]);
    }
}

// ---------------- conv2: 32->64, K=15, stride 2, pad 7 (f32x2, 512 thr) ----------------
#define CONV2_SM ((2*32*264 + 30720 + 64)*4)
__global__ void k_conv2(const float* __restrict__ w, const float* __restrict__ bias){
    extern __shared__ float sm[];
    float* sInE = sm;               // [32][264]  even positions
    float* sInO = sm + 32*264;      // [32][264]  odd positions
    float* sW2  = sm + 2*32*264;    // [k][ci][co] 15*32*64
    float* sb   = sW2 + 30720;      // 64
    int tid = threadIdx.x;
    int b  = blockIdx.y;
    int t0 = blockIdx.x*256;
    for (int i = tid; i < 30720; i += 512){
        int co = i/480, rem = i - co*480;
        int ci = rem/15, k = rem - ci*15;
        sW2[(k*32+ci)*64 + co] = w[i];
    }
    if (tid < 64) sb[tid] = bias[tid];
    int pbase = 2*t0 - 7;
    for (int i = tid; i < 32*525; i += 512){
        int ci = i/525, s = i - ci*525;
        int p  = pbase + s;
        float v = (p >= 0 && p < T1) ? g_h1[(b*32+ci)*T1 + p] : 0.f;
        if (s & 1) sInO[ci*264 + (s>>1)] = v;
        else       sInE[ci*264 + (s>>1)] = v;
    }
    __syncthreads();
    int tx = tid & 31, wrp = tid >> 5;
    int co0 = (wrp >> 1)*8;
    int tt0 = (wrp & 1)*128 + tx;
    uint64_t ap[4][4];
    #pragma unroll
    for (int pu = 0; pu < 4; pu++)
        #pragma unroll
        for (int j = 0; j < 4; j++) ap[pu][j] = 0ull;
    for (int k = 0; k < 15; k++){
        const float* xa = (k & 1) ? sInO : sInE;
        int kb = k >> 1;
        #pragma unroll 4
        for (int ci = 0; ci < 32; ci++){
            const ulonglong2* wp = (const ulonglong2*)&sW2[(k*32+ci)*64 + co0];
            ulonglong2 wA = wp[0];
            ulonglong2 wB = wp[1];
            float x0 = xa[ci*264 + tt0      + kb];
            float x1 = xa[ci*264 + tt0 + 32 + kb];
            float x2 = xa[ci*264 + tt0 + 64 + kb];
            float x3 = xa[ci*264 + tt0 + 96 + kb];
            uint64_t xd0 = dup2(x0), xd1 = dup2(x1), xd2 = dup2(x2), xd3 = dup2(x3);
            ffma2(ap[0][0], wA.x, xd0); ffma2(ap[0][1], wA.x, xd1); ffma2(ap[0][2], wA.x, xd2); ffma2(ap[0][3], wA.x, xd3);
            ffma2(ap[1][0], wA.y, xd0); ffma2(ap[1][1], wA.y, xd1); ffma2(ap[1][2], wA.y, xd2); ffma2(ap[1][3], wA.y, xd3);
            ffma2(ap[2][0], wB.x, xd0); ffma2(ap[2][1], wB.x, xd1); ffma2(ap[2][2], wB.x, xd2); ffma2(ap[2][3], wB.x, xd3);
            ffma2(ap[3][0], wB.y, xd0); ffma2(ap[3][1], wB.y, xd1); ffma2(ap[3][2], wB.y, xd2); ffma2(ap[3][3], wB.y, xd3);
        }
    }
    #pragma unroll
    for (int pu = 0; pu < 4; pu++){
        int coA = co0 + 2*pu, coB = coA + 1;
        float bA = sb[coA], bB = sb[coB];
        #pragma unroll
        for (int j = 0; j < 4; j++){
            float aA, aB;
            unpk(aA, aB, ap[pu][j]);
            int t = t0 + tt0 + 32*j;
            g_h2[(b*64+coA)*T2 + t] = lrelu(aA + bA);
            g_h2[(b*64+coB)*T2 + t] = lrelu(aB + bB);
        }
    }
}

// ---------------- conv3: 64->64, K=3, stride 1, pad 1 (f32x2, co-packed) ----------------
#define CONV3_SM ((64*132 + 12288 + 64)*4)
__global__ void k_conv3(const float* __restrict__ w, const float* __restrict__ bias){
    extern __shared__ float sm[];
    float* sIn = sm;               // 64 x 132 (span 130)
    float* sW3 = sm + 64*132;      // [k][ci][co] 3*64*64
    float* sb  = sW3 + 12288;
    int tid = threadIdx.x;
    int b  = blockIdx.y;
    int t0 = blockIdx.x*128;
    for (int i = tid; i < 12288; i += 256){
        int co = i/192, rem = i - co*192;
        int ci = rem/3, k = rem - ci*3;
        sW3[(k*64+ci)*64 + co] = w[i];
    }
    if (tid < 64) sb[tid] = bias[tid];
    int pbase = t0 - 1;
    for (int i = tid; i < 64*130; i += 256){
        int ci = i/130, s = i - ci*130;
        int p  = pbase + s;
        sIn[ci*132+s] = (p >= 0 && p < T2) ? g_h2[(b*64+ci)*T2 + p] : 0.f;
    }
    __syncthreads();
    int tx = tid & 31, ty = tid >> 5;
    int co0 = ty*8;
    uint64_t ap[4][4];
    #pragma unroll
    for (int pu = 0; pu < 4; pu++)
        #pragma unroll
        for (int j = 0; j < 4; j++) ap[pu][j] = 0ull;
    #pragma unroll
    for (int k = 0; k < 3; k++){
        #pragma unroll 4
        for (int ci = 0; ci < 64; ci++){
            const ulonglong2* wp = (const ulonglong2*)&sW3[(k*64+ci)*64 + co0];
            ulonglong2 wA = wp[0];
            ulonglong2 wB = wp[1];
            float x0 = sIn[ci*132 + tx      + k];
            float x1 = sIn[ci*132 + tx + 32 + k];
            float x2 = sIn[ci*132 + tx + 64 + k];
            float x3 = sIn[ci*132 + tx + 96 + k];
            uint64_t xd0 = dup2(x0), xd1 = dup2(x1), xd2 = dup2(x2), xd3 = dup2(x3);
            ffma2(ap[0][0], wA.x, xd0); ffma2(ap[0][1], wA.x, xd1); ffma2(ap[0][2], wA.x, xd2); ffma2(ap[0][3], wA.x, xd3);
            ffma2(ap[1][0], wA.y, xd0); ffma2(ap[1][1], wA.y, xd1); ffma2(ap[1][2], wA.y, xd2); ffma2(ap[1][3], wA.y, xd3);
            ffma2(ap[2][0], wB.x, xd0); ffma2(ap[2][1], wB.x, xd1); ffma2(ap[2][2], wB.x, xd2); ffma2(ap[2][3], wB.x, xd3);
            ffma2(ap[3][0], wB.y, xd0); ffma2(ap[3][1], wB.y, xd1); ffma2(ap[3][2], wB.y, xd2); ffma2(ap[3][3], wB.y, xd3);
        }
    }
    #pragma unroll
    for (int pu = 0; pu < 4; pu++){
        int coA = co0 + 2*pu, coB = coA + 1;
        float bA = sb[coA], bB = sb[coB];
        #pragma unroll
        for (int j = 0; j < 4; j++){
            float aA, aB;
            unpk(aA, aB, ap[pu][j]);
            int t = t0 + tx + 32*j;
            g_z[(b*64+coA)*T2 + t] = aA + bA;
            g_z[(b*64+coB)*T2 + t] = aB + bB;
        }
    }
}

// ---------------- VQ: 128 rows; 4 rows x 16 codes per warp per chunk ----------
#define SZS 132
#define CT_S 132
#define VQ_SM ((64*SZS + 128 + 64*CT_S + 256)*4)
__global__ void k_vq(const float* __restrict__ cb, float* __restrict__ out_idxf){
    extern __shared__ float sm[];
    float* sZ  = sm;                  // [d][row] 64 x SZS (128 rows used)
    float* szn = sm + 64*SZS;         // 128 row norms
    float* sCbT= szn + 128;           // transposed chunk [64][CT_S] (128 codes)
    float* scn = sCbT + 64*CT_S;      // 128 code norms (+ loss partial area)
    float* redD = sCbT;               // reuse after chunks
    int*   redI = (int*)(sCbT + 1024);
    int*   sIdx = (int*)(sCbT + 2048);
    int tid = threadIdx.x;
    int row0 = blockIdx.x*128;
    int b  = row0 >> 12;
    int t0 = row0 & 4095;
    for (int i = tid; i < 8192; i += 256){
        int d = i >> 7, rr = i & 127;
        sZ[d*SZS + rr] = g_z[(b*64+d)*T2 + t0 + rr];
    }
    __syncthreads();
    int lane = tid & 31, w = tid >> 5;
    #pragma unroll
    for (int q = 0; q < 16; q++){
        int rr = w*16 + q;
        float v0 = sZ[(2*lane  )*SZS + rr];
        float v1 = sZ[(2*lane+1)*SZS + rr];
        float p = __fmul_rn(v0, v0);
        p = __fadd_rn(p, __fmul_rn(v1, v1));
        p = warp_tree_sum(p);
        if (lane == 0) szn[rr] = p;
    }
    __syncthreads();
    int rb = lane*4;
    float zn[4];
    #pragma unroll
    for (int i = 0; i < 4; i++) zn[i] = szn[rb+i];
    float bd[4] = {3.4e38f, 3.4e38f, 3.4e38f, 3.4e38f};
    int   bi[4] = {0,0,0,0};
    int c0 = w*16;
    for (int ch = 0; ch < 8; ch++){
        for (int i = tid; i < 8192; i += 256){
            int d = i & 63, c = i >> 6;
            sCbT[d*CT_S + c] = cb[(ch*128+c)*64 + d];
        }
        if (tid < 128) scn[tid] = g_cn[ch*128 + tid];
        __syncthreads();
        uint64_t pr[4][8];
        #pragma unroll
        for (int i = 0; i < 4; i++)
            #pragma unroll
            for (int jp = 0; jp < 8; jp++) pr[i][jp] = 0ull;
        #pragma unroll 2
        for (int d = 0; d < 64; d++){
            float4 zv = *(const float4*)&sZ[d*SZS + rb];
            uint64_t zd0 = dup2(zv.x), zd1 = dup2(zv.y), zd2 = dup2(zv.z), zd3 = dup2(zv.w);
            ulonglong2 cpA = *(const ulonglong2*)&sCbT[d*CT_S + c0];
            ulonglong2 cpB = *(const ulonglong2*)&sCbT[d*CT_S + c0 + 4];
            ffma2(pr[0][0], zd0, cpA.x); ffma2(pr[1][0], zd1, cpA.x); ffma2(pr[2][0], zd2, cpA.x); ffma2(pr[3][0], zd3, cpA.x);
            ffma2(pr[0][1], zd0, cpA.y); ffma2(pr[1][1], zd1, cpA.y); ffma2(pr[2][1], zd2, cpA.y); ffma2(pr[3][1], zd3, cpA.y);
            ffma2(pr[0][2], zd0, cpB.x); ffma2(pr[1][2], zd1, cpB.x); ffma2(pr[2][2], zd2, cpB.x); ffma2(pr[3][2], zd3, cpB.x);
            ffma2(pr[0][3], zd0, cpB.y); ffma2(pr[1][3], zd1, cpB.y); ffma2(pr[2][3], zd2, cpB.y); ffma2(pr[3][3], zd3, cpB.y);
            ulonglong2 cpC = *(const ulonglong2*)&sCbT[d*CT_S + c0 + 8];
            ulonglong2 cpD = *(const ulonglong2*)&sCbT[d*CT_S + c0 + 12];
            ffma2(pr[0][4], zd0, cpC.x); ffma2(pr[1][4], zd1, cpC.x); ffma2(pr[2][4], zd2, cpC.x); ffma2(pr[3][4], zd3, cpC.x);
            ffma2(pr[0][5], zd0, cpC.y); ffma2(pr[1][5], zd1, cpC.y); ffma2(pr[2][5], zd2, cpC.y); ffma2(pr[3][5], zd3, cpC.y);
            ffma2(pr[0][6], zd0, cpD.x); ffma2(pr[1][6], zd1, cpD.x); ffma2(pr[2][6], zd2, cpD.x); ffma2(pr[3][6], zd3, cpD.x);
            ffma2(pr[0][7], zd0, cpD.y); ffma2(pr[1][7], zd1, cpD.y); ffma2(pr[2][7], zd2, cpD.y); ffma2(pr[3][7], zd3, cpD.y);
        }
        #pragma unroll
        for (int jp = 0; jp < 8; jp++){
            int gc0 = ch*128 + c0 + 2*jp;
            float cnL = scn[c0 + 2*jp];
            float cnH = scn[c0 + 2*jp + 1];
            #pragma unroll
            for (int i = 0; i < 4; i++){
                float aL, aH;
                unpk(aL, aH, pr[i][jp]);
                float sL = __fadd_rn(zn[i], cnL);
                float dL = __fsub_rn(sL, __fmul_rn(2.0f, aL));
                if (dL < bd[i]){ bd[i] = dL; bi[i] = gc0; }
                float sH = __fadd_rn(zn[i], cnH);
                float dH = __fsub_rn(sH, __fmul_rn(2.0f, aH));
                if (dH < bd[i]){ bd[i] = dH; bi[i] = gc0 + 1; }
            }
        }
        __syncthreads();
    }
    #pragma unroll
    for (int i = 0; i < 4; i++){ redD[w*128 + rb + i] = bd[i]; redI[w*128 + rb + i] = bi[i]; }
    __syncthreads();
    if (tid < 128){
        float d0 = redD[tid]; int i0 = redI[tid];
        #pragma unroll
        for (int g2 = 1; g2 < 8; g2++){
            float dg = redD[g2*128 + tid]; int ig = redI[g2*128 + tid];
            if (dg < d0 || (dg == d0 && ig < i0)){ d0 = dg; i0 = ig; }
        }
        g_idx[row0 + tid] = i0;
        out_idxf[row0 + tid] = (float)i0;
        sIdx[tid] = i0;
    }
    __syncthreads();
    int row = tid & 127, dh = (tid >> 7)*32;
    int id = sIdx[row];
    const float* cq = cb + id*64 + dh;
    float lsum = 0.f;
    #pragma unroll 4
    for (int dq = 0; dq < 32; dq += 4){
        float4 q = *(const float4*)&cq[dq];
        float z0 = sZ[(dh+dq+0)*SZS + row];
        float z1 = sZ[(dh+dq+1)*SZS + row];
        float z2 = sZ[(dh+dq+2)*SZS + row];
        float z3 = sZ[(dh+dq+3)*SZS + row];
        float f0 = __fsub_rn(q.x, z0), f1 = __fsub_rn(q.y, z1);
        float f2 = __fsub_rn(q.z, z2), f3 = __fsub_rn(q.w, z3);
        g_quant[(b*64 + dh+dq+0)*T2 + t0 + row] = __fadd_rn(z0, f0);
        g_quant[(b*64 + dh+dq+1)*T2 + t0 + row] = __fadd_rn(z1, f1);
        g_quant[(b*64 + dh+dq+2)*T2 + t0 + row] = __fadd_rn(z2, f2);
        g_quant[(b*64 + dh+dq+3)*T2 + t0 + row] = __fadd_rn(z3, f3);
        lsum += f0*f0; lsum += f1*f1; lsum += f2*f2; lsum += f3*f3;
    }
    __syncthreads();
    scn[tid] = lsum;
    __syncthreads();
    for (int s = 128; s > 0; s >>= 1){
        if (tid < s) scn[tid] += scn[tid + s];
        __syncthreads();
    }
    if (tid == 0) g_part[blockIdx.x] = scn[0];
}

__global__ void k_loss(float* __restrict__ out){
    __shared__ float red[256];
    int tid = threadIdx.x;
    float a = 0.f;
    for (int i = tid; i < 1024; i += 256) a += g_part[i];
    red[tid] = a; __syncthreads();
    for (int s = 128; s > 0; s >>= 1){
        if (tid < s) red[tid] += red[tid + s];
        __syncthreads();
    }
    if (tid == 0) out[B*T0] = 1.25f * red[0] / 8388608.0f;
}

// ---------------- deconv1: ConvT 64->64, K=4, stride 2, pad 1 (f32x2, R12 shape) ----------------
#define DC1_SM ((64*68 + 16384 + 64)*4)
__global__ void k_deconv1(const float* __restrict__ w, const float* __restrict__ bias){
    extern __shared__ float sm[];
    float* sIn = sm;               // 64 x 68 (span 66: m0-1..m0+64)
    float* sW  = sm + 64*68;       // 64*64*4, k-swizzled
    float* sb  = sW + 16384;
    int tid = threadIdx.x;
    int b  = blockIdx.y;
    int m0 = blockIdx.x*64;
    for (int i = tid; i < 16384; i += 256) sW[i^1] = w[i];   // swizzle k: 0<->1, 2<->3
    if (tid < 64) sb[tid] = bias[tid];
    for (int i = tid; i < 64*66; i += 256){
        int ci = i/66, s = i - ci*66;
        int t = m0 - 1 + s;
        sIn[ci*68+s] = (t >= 0 && t < T2) ? g_quant[(b*64+ci)*T2 + t] : 0.f;
    }
    __syncthreads();
    int tx = tid & 31, ty = tid >> 5;
    int co0 = ty*8;
    uint64_t py[8][2];   // [u][j], packed {ye,yo}
    #pragma unroll
    for (int u = 0; u < 8; u++){ py[u][0] = 0ull; py[u][1] = 0ull; }
    for (int i = 0; i < 64; i++){
        uint64_t pA[2], pB[2];
        #pragma unroll
        for (int j = 0; j < 2; j++){
            int s = tx + 32*j;
            float xm1 = sIn[i*68 + s];
            float xm  = sIn[i*68 + s + 1];
            float xp1 = sIn[i*68 + s + 2];
            pA[j] = pack2(xm, xp1);
            pB[j] = pack2(xm1, xm);
        }
        #pragma unroll
        for (int u = 0; u < 8; u++){
            ulonglong2 wp = *(const ulonglong2*)&sW[(i*64 + co0 + u)*4]; // {w1,w0},{w3,w2}
            #pragma unroll
            for (int j = 0; j < 2; j++){
                ffma2(py[u][j], pA[j], wp.x);
                ffma2(py[u][j], pB[j], wp.y);
            }
        }
    }
    #pragma unroll
    for (int u = 0; u < 8; u++){
        float bb = sb[co0+u];
        #pragma unroll
        for (int j = 0; j < 2; j++){
            int m = m0 + tx + 32*j;
            float ye, yo;
            unpk(ye, yo, py[u][j]);
            float2 o;
            o.x = lrelu(ye + bb);
            o.y = lrelu(yo + bb);
            *(float2*)&g_d1[(b*64 + co0 + u)*T1 + 2*m] = o;
        }
    }
}

// ------- deconv2 + out conv FUSED: ConvT 64->32 (K=4,s2,p1) -> conv 32->1 (K=7,p3) + tanh ----
// m-tile 128 with +-2 halo (132 m-values -> d2 t' range [2m0-4, 2m0+260) = 264 cols).
// d2 staged in smem; out conv reads it with identical ci-then-k fmaf chain. Bit-exact.
#define DOUT_SM ((64*136 + 8192 + 32 + 32*268 + 224 + 8)*4)
__global__ void k_deconv2out(const float* __restrict__ w, const float* __restrict__ bias,
                             const float* __restrict__ ow, const float* __restrict__ ob,
                             float* __restrict__ out){
    extern __shared__ float sm[];
    float* sIn = sm;                 // [64][136]  d1, positions m0-3 .. m0+130 (span 134)
    float* sW  = sm + 64*136;        // 64*32*4, k-swizzled
    float* sb  = sW + 8192;          // 32
    float* sD2 = sb + 32;            // [32][268]  d2, t' = 2m0-4 .. 2m0+259 (264 used)
    float* sow = sD2 + 32*268;       // 224
    float* sob = sow + 224;          // 1
    int tid = threadIdx.x;
    int b  = blockIdx.y;
    int m0 = blockIdx.x*128;
    for (int i = tid; i < 8192; i += 256) sW[i^1] = w[i];    // (w1,w0,w3,w2)
    if (tid < 32) sb[tid] = bias[tid];
    for (int i = tid; i < 224; i += 256) sow[i] = ow[i];
    if (tid == 0) sob[0] = ob[0];
    for (int i = tid; i < 64*134; i += 256){
        int ci = i/134, s = i - ci*134;
        int t = m0 - 3 + s;
        sIn[ci*136+s] = (t >= 0 && t < T1) ? g_d1[(b*64+ci)*T1 + t] : 0.f;
    }
    __syncthreads();
    int tx = tid & 31, ty = tid >> 5;
    int co0 = ty*4;
    // j = 0..4 ; m = m0-2 + tx + 32j ; j==4 active only for tx<4 (m up to m0+129)
    uint64_t py[4][5];
    #pragma unroll
    for (int u = 0; u < 4; u++)
        #pragma unroll
        for (int j = 0; j < 5; j++) py[u][j] = 0ull;
    for (int i = 0; i < 64; i++){
        uint64_t pA[5], pB[5];
        #pragma unroll
        for (int j = 0; j < 5; j++){
            int s = tx + 32*j;                    // sIn offset for m-1 (since sIn starts at m0-3, m-1 = m0-3 + tx+32j)
            if (j < 4 || tx < 4){
                float xm1 = sIn[i*136 + s];
                float xm  = sIn[i*136 + s + 1];
                float xp1 = sIn[i*136 + s + 2];
                pA[j] = pack2(xm, xp1);
                pB[j] = pack2(xm1, xm);
            } else { pA[j] = 0ull; pB[j] = 0ull; }
        }
        #pragma unroll
        for (int u = 0; u < 4; u++){
            ulonglong2 wp = *(const ulonglong2*)&sW[(i*32 + co0 + u)*4]; // {w1,w0},{w3,w2}
            #pragma unroll
            for (int j = 0; j < 5; j++){
                ffma2(py[u][j], pA[j], wp.x);
                ffma2(py[u][j], pB[j], wp.y);
            }
        }
    }
    #pragma unroll
    for (int u = 0; u < 4; u++){
        float bb = sb[co0+u];
        #pragma unroll
        for (int j = 0; j < 5; j++){
            if (j == 4 && tx >= 4) continue;
            int m = m0 - 2 + tx + 32*j;
            int off = 2*(tx + 32*j);              // t' - (2m0-4)
            float ye, yo;
            unpk(ye, yo, py[u][j]);
            bool valid = (m >= 0 && m < T1);
            sD2[(co0+u)*268 + off    ] = valid ? lrelu(ye + bb) : 0.f;
            sD2[(co0+u)*268 + off + 1] = valid ? lrelu(yo + bb) : 0.f;
        }
    }
    __syncthreads();
    // out conv: 256 threads -> 256 outputs t = 2m0 + tid
    // d2[t + k - 3] = sD2[ci][tid + k + 1]   (identical chain to old k_out)
    float a = 0.f;
    for (int ci = 0; ci < 32; ci++){
        #pragma unroll
        for (int k = 0; k < 7; k++) a = fmaf(sow[ci*7+k], sD2[ci*268 + tid + k + 1], a);
    }
    out[b*T0 + 2*m0 + tid] = tanhf(a + sob[0]);
}

// ---------------- launch ----------------
extern "C" void kernel_launch(void* const* d_in, const int* in_sizes, int n_in,
                              void* d_out, int out_size){
    (void)in_sizes; (void)n_in; (void)out_size;
    const float* x   = (const float*)d_in[0];
    const float* c1w = (const float*)d_in[1];
    const float* c1b = (const float*)d_in[2];
    const float* c2w = (const float*)d_in[3];
    const float* c2b = (const float*)d_in[4];
    const float* c3w = (const float*)d_in[5];
    const float* c3b = (const float*)d_in[6];
    const float* cb  = (const float*)d_in[7];
    const float* d1w = (const float*)d_in[8];
    const float* d1b = (const float*)d_in[9];
    const float* d2w = (const float*)d_in[10];
    const float* d2b = (const float*)d_in[11];
    const float* ow  = (const float*)d_in[12];
    const float* ob  = (const float*)d_in[13];
    float* out = (float*)d_out;

    cudaFuncSetAttribute(k_conv2,     cudaFuncAttributeMaxDynamicSharedMemorySize, CONV2_SM);
    cudaFuncSetAttribute(k_conv3,     cudaFuncAttributeMaxDynamicSharedMemorySize, CONV3_SM);
    cudaFuncSetAttribute(k_vq,        cudaFuncAttributeMaxDynamicSharedMemorySize, VQ_SM);
    cudaFuncSetAttribute(k_deconv1,   cudaFuncAttributeMaxDynamicSharedMemorySize, DC1_SM);
    cudaFuncSetAttribute(k_deconv2out,cudaFuncAttributeMaxDynamicSharedMemorySize, DOUT_SM);

    // k_vq is launch #4 -> lands in the ncu-profiled slot.
    k_conv1    <<<1152, 256>>>(x, c1w, c1b, cb);       // +128 blocks do cnorm
    k_conv2    <<<dim3(16,32), 512, CONV2_SM>>>(c2w, c2b);
    k_conv3    <<<dim3(32,32), 256, CONV3_SM>>>(c3w, c3b);
    k_vq       <<<1024, 256, VQ_SM>>>(cb, out + B*T0 + 1);
    k_loss     <<<1, 256>>>(out);
    k_deconv1  <<<dim3(64,32), 256, DC1_SM>>>(d1w, d1b);
    k_deconv2out<<<dim3(64,32), 256, DOUT_SM>>>(d2w, d2b, ow, ob, out);
}